// round 10
// baseline (speedup 1.0000x reference)
#include <cuda_runtime.h>

#define BB 512
#define KK 800
#define DD 512
#define LL 500000
#define NB 24
#define BSZ ((LL + NB - 1) / NB)   // 20834; last bucket slightly smaller

// ---------------------------------------------------------------------------
// Single fused kernel. grid = (x=b fast, y=bucket slow), 256 threads.
// Per block (b,bucket): stage embed[b] in shared + filter this bucket's items
// out of shortlist row b (one int4 per thread, warp-aggregated compaction),
// ONE barrier, then warp-per-item float4 dot products.
//
// Linear bid order => the ~1184 concurrently-resident blocks span ~2.3
// buckets => concurrent weight footprint ~96 MB < 126 MB L2, so duplicate
// weight rows across b are L2 hits; DRAM traffic == unique rows (~573 MB).
// Weight loads use __ldcg (L2-only): rows are reused across blocks via L2,
// never within a block via L1, so L1 allocation is pure overhead.
// ---------------------------------------------------------------------------
__global__ __launch_bounds__(256, 8) void fused_kernel(
    const float* __restrict__ embed,
    const int*   __restrict__ shortlist,
    const float* __restrict__ sp_weight,
    const float* __restrict__ sp_bias,
    float*       __restrict__ out)
{
    __shared__ float4       s_embed[DD / 4];   // 2 KB
    __shared__ unsigned int s_list[KK];
    __shared__ int          s_cnt;

    const int b      = blockIdx.x;
    const int bucket = blockIdx.y;
    const int t      = threadIdx.x;
    const int lane   = t & 31;

    if (t == 0) s_cnt = 0;
    __syncthreads();

    // ---- overlapped prologue: embed staging + shortlist filter ----
    const float4* erow = reinterpret_cast<const float4*>(embed + (size_t)b * DD);
    if (t < DD / 4)                    // 128 threads, 1 float4 each
        s_embed[t] = erow[t];

    const int lo = bucket * BSZ;
    const int hi = lo + BSZ;           // last bucket: hi > LL harmless (idx < LL)

    const int4* srow = reinterpret_cast<const int4*>(shortlist + (size_t)b * KK);
    int4 v = make_int4(-1, -1, -1, -1);
    if (t < KK / 4)                    // 200 threads, 1 int4 each
        v = srow[t];

    // warp-aggregated compaction, component by component
    #pragma unroll
    for (int c = 0; c < 4; ++c) {
        int idx = (c == 0) ? v.x : (c == 1) ? v.y : (c == 2) ? v.z : v.w;
        bool m = (t < KK / 4) && (idx >= lo) && (idx < hi);
        unsigned bal = __ballot_sync(0xffffffffu, m);
        if (bal) {
            int base = 0;
            if (lane == 0) base = atomicAdd(&s_cnt, __popc(bal));
            base = __shfl_sync(0xffffffffu, base, 0);
            if (m) {
                int off = __popc(bal & ((1u << lane) - 1u));
                int k = t * 4 + c;
                s_list[base + off] = ((unsigned)idx << 10) | (unsigned)k;
            }
        }
    }
    __syncthreads();

    // ---- main: warp per item, float4-coalesced weight-row dot ----
    const int cnt  = s_cnt;
    const int warp = t >> 5;

    for (int j = warp; j < cnt; j += 8) {
        const unsigned int it  = s_list[j];
        const int          k   = (int)(it & 1023u);
        const long long    idx = (long long)(it >> 10);

        const float4* wrow =
            reinterpret_cast<const float4*>(sp_weight + idx * DD);

        float sum = 0.0f;
        #pragma unroll
        for (int i = 0; i < DD / 128; ++i) {   // 4 independent LDG.128.CG
            float4 w = __ldcg(wrow + i * 32 + lane);
            float4 e = s_embed[i * 32 + lane];
            sum = fmaf(w.x, e.x, sum);
            sum = fmaf(w.y, e.y, sum);
            sum = fmaf(w.z, e.z, sum);
            sum = fmaf(w.w, e.w, sum);
        }

        #pragma unroll
        for (int off = 16; off; off >>= 1)
            sum += __shfl_xor_sync(0xffffffffu, sum, off);

        if (lane == 0)
            out[b * KK + k] = sum + __ldg(&sp_bias[idx]);
    }
}

extern "C" void kernel_launch(void* const* d_in, const int* in_sizes, int n_in,
                              void* d_out, int out_size) {
    const float* embed     = (const float*)d_in[0];
    const int*   shortlist = (const int*)  d_in[1];
    const float* sp_weight = (const float*)d_in[2];
    const float* sp_bias   = (const float*)d_in[3];
    float*       out       = (float*)d_out;

    fused_kernel<<<dim3(BB, NB), 256>>>(embed, shortlist, sp_weight, sp_bias, out);
}

// round 11
// speedup vs baseline: 1.0834x; 1.0834x over previous
#include <cuda_runtime.h>

#define BB 512
#define KK 800
#define DD 512
#define LL 500000
#define NB 24
#define BSZ ((LL + NB - 1) / NB)   // 20834; last bucket slightly smaller

// ---------------------------------------------------------------------------
// Single fused kernel. grid = (x=b fast, y=bucket slow), 256 threads.
// Per block (b,bucket):
//   1. stage embed[b] in shared + filter this bucket's items from shortlist
//      row b (one int4/thread, warp-aggregated compaction)
//   2. bitonic-sort the compacted items by idx (packed key) so every
//      co-resident block on an SM sweeps the bucket's idx range in the SAME
//      ascending order -> cross-block same-SM row reuse hits in L1 (~32cyc)
//      instead of L2 (~250cyc)  [R10's __ldcg regression proved L1 hits are
//      a significant latency reducer here]
//   3. warp per item: float4-coalesced weight-row dot + shuffle reduction
//
// Linear bid order => concurrent blocks share a ~96 MB weight window < L2,
// so duplicate rows across b are L2 hits; DRAM traffic == unique rows.
// ---------------------------------------------------------------------------
__global__ __launch_bounds__(256, 8) void fused_kernel(
    const float* __restrict__ embed,
    const int*   __restrict__ shortlist,
    const float* __restrict__ sp_weight,
    const float* __restrict__ sp_bias,
    float*       __restrict__ out)
{
    __shared__ float4       s_embed[DD / 4];   // 2 KB
    __shared__ unsigned int s_list[1024];      // compacted items, pow2 capacity
    __shared__ int          s_cnt;

    const int b      = blockIdx.x;
    const int bucket = blockIdx.y;
    const int t      = threadIdx.x;
    const int lane   = t & 31;

    if (t == 0) s_cnt = 0;
    __syncthreads();

    // ---- overlapped prologue: embed staging + shortlist filter ----
    const float4* erow = reinterpret_cast<const float4*>(embed + (size_t)b * DD);
    if (t < DD / 4)                    // 128 threads, 1 float4 each
        s_embed[t] = erow[t];

    const int lo = bucket * BSZ;
    const int hi = lo + BSZ;           // last bucket: hi > LL harmless (idx < LL)

    const int4* srow = reinterpret_cast<const int4*>(shortlist + (size_t)b * KK);
    int4 v = make_int4(-1, -1, -1, -1);
    if (t < KK / 4)                    // 200 threads, 1 int4 each
        v = srow[t];

    // warp-aggregated compaction, component by component
    #pragma unroll
    for (int c = 0; c < 4; ++c) {
        int idx = (c == 0) ? v.x : (c == 1) ? v.y : (c == 2) ? v.z : v.w;
        bool m = (t < KK / 4) && (idx >= lo) && (idx < hi);
        unsigned bal = __ballot_sync(0xffffffffu, m);
        if (bal) {
            int base = 0;
            if (lane == 0) base = atomicAdd(&s_cnt, __popc(bal));
            base = __shfl_sync(0xffffffffu, base, 0);
            if (m) {
                int off = __popc(bal & ((1u << lane) - 1u));
                int k = t * 4 + c;
                s_list[base + off] = ((unsigned)idx << 10) | (unsigned)k;
            }
        }
    }
    __syncthreads();

    // ---- sort items by idx (packed key sorts by idx first) ----
    const int cnt = s_cnt;
    int P = 1;
    while (P < cnt) P <<= 1;           // next pow2 (same in all threads)
    for (int i = cnt + t; i < P; i += 256)
        s_list[i] = 0xFFFFFFFFu;       // +inf padding sorts to the tail
    __syncthreads();

    for (int ksz = 2; ksz <= P; ksz <<= 1) {
        for (int j = ksz >> 1; j > 0; j >>= 1) {
            for (int i = t; i < P; i += 256) {
                int ixj = i ^ j;
                if (ixj > i) {
                    unsigned a = s_list[i], c2 = s_list[ixj];
                    bool up = ((i & ksz) == 0);
                    if ((a > c2) == up) { s_list[i] = c2; s_list[ixj] = a; }
                }
            }
            __syncthreads();
        }
    }

    // ---- main: warp per item (ascending idx), float4 weight-row dot ----
    const int warp = t >> 5;

    for (int j = warp; j < cnt; j += 8) {
        const unsigned int it  = s_list[j];
        const int          k   = (int)(it & 1023u);
        const long long    idx = (long long)(it >> 10);

        const float4* wrow =
            reinterpret_cast<const float4*>(sp_weight + idx * DD);

        float sum = 0.0f;
        #pragma unroll
        for (int i = 0; i < DD / 128; ++i) {   // 4 independent LDG.128
            float4 w = wrow[i * 32 + lane];
            float4 e = s_embed[i * 32 + lane];
            sum = fmaf(w.x, e.x, sum);
            sum = fmaf(w.y, e.y, sum);
            sum = fmaf(w.z, e.z, sum);
            sum = fmaf(w.w, e.w, sum);
        }

        #pragma unroll
        for (int off = 16; off; off >>= 1)
            sum += __shfl_xor_sync(0xffffffffu, sum, off);

        if (lane == 0)
            out[b * KK + k] = sum + __ldg(&sp_bias[idx]);
    }
}

extern "C" void kernel_launch(void* const* d_in, const int* in_sizes, int n_in,
                              void* d_out, int out_size) {
    const float* embed     = (const float*)d_in[0];
    const int*   shortlist = (const int*)  d_in[1];
    const float* sp_weight = (const float*)d_in[2];
    const float* sp_bias   = (const float*)d_in[3];
    float*       out       = (float*)d_out;

    fused_kernel<<<dim3(BB, NB), 256>>>(embed, shortlist, sp_weight, sp_bias, out);
}

// round 12
// speedup vs baseline: 1.2644x; 1.1671x over previous
#include <cuda_runtime.h>

#define BB 512
#define KK 800
#define DD 512
#define LL 500000
#define NB 24
#define BSZ ((LL + NB - 1) / NB)   // 20834; last bucket slightly smaller

// ---------------------------------------------------------------------------
// Single fused kernel. grid = (x=b fast, y=bucket slow), 256 threads.
// Per block (b,bucket): stage embed[b] in shared + filter this bucket's items
// out of shortlist row b (one int4 per thread, warp-aggregated compaction),
// ONE barrier, then warp-per-item float4 dot products.
//
// Linear bid order => the ~1184 concurrently-resident blocks span ~2.3
// buckets => concurrent weight footprint ~96 MB < 126 MB L2, so duplicate
// weight rows across b are L2 hits; DRAM traffic == unique rows (~573 MB),
// the floor for this problem at fp32. Plain LDG.128 (default caching) is
// deliberate: L1 serves cross-block same-SM row reuse (R10's __ldcg test
// showed bypassing L1 costs 1.15 TB/s). Minimal barriers are deliberate:
// barrier-coupling warps/blocks (R9 persistent, R11 sort) costs 10+ us.
// ---------------------------------------------------------------------------
__global__ __launch_bounds__(256, 8) void fused_kernel(
    const float* __restrict__ embed,
    const int*   __restrict__ shortlist,
    const float* __restrict__ sp_weight,
    const float* __restrict__ sp_bias,
    float*       __restrict__ out)
{
    __shared__ float4       s_embed[DD / 4];   // 2 KB
    __shared__ unsigned int s_list[KK];
    __shared__ int          s_cnt;

    const int b      = blockIdx.x;
    const int bucket = blockIdx.y;
    const int t      = threadIdx.x;
    const int lane   = t & 31;

    if (t == 0) s_cnt = 0;
    __syncthreads();

    // ---- overlapped prologue: embed staging + shortlist filter ----
    const float4* erow = reinterpret_cast<const float4*>(embed + (size_t)b * DD);
    if (t < DD / 4)                    // 128 threads, 1 float4 each
        s_embed[t] = erow[t];

    const int lo = bucket * BSZ;
    const int hi = lo + BSZ;           // last bucket: hi > LL harmless (idx < LL)

    const int4* srow = reinterpret_cast<const int4*>(shortlist + (size_t)b * KK);
    int4 v = make_int4(-1, -1, -1, -1);
    if (t < KK / 4)                    // 200 threads, 1 int4 each
        v = srow[t];

    // warp-aggregated compaction, component by component
    #pragma unroll
    for (int c = 0; c < 4; ++c) {
        int idx = (c == 0) ? v.x : (c == 1) ? v.y : (c == 2) ? v.z : v.w;
        bool m = (t < KK / 4) && (idx >= lo) && (idx < hi);
        unsigned bal = __ballot_sync(0xffffffffu, m);
        if (bal) {
            int base = 0;
            if (lane == 0) base = atomicAdd(&s_cnt, __popc(bal));
            base = __shfl_sync(0xffffffffu, base, 0);
            if (m) {
                int off = __popc(bal & ((1u << lane) - 1u));
                int k = t * 4 + c;
                s_list[base + off] = ((unsigned)idx << 10) | (unsigned)k;
            }
        }
    }
    __syncthreads();

    // ---- main: warp per item, float4-coalesced weight-row dot ----
    const int cnt  = s_cnt;
    const int warp = t >> 5;

    for (int j = warp; j < cnt; j += 8) {
        const unsigned int it  = s_list[j];
        const int          k   = (int)(it & 1023u);
        const long long    idx = (long long)(it >> 10);

        const float4* wrow =
            reinterpret_cast<const float4*>(sp_weight + idx * DD);

        float sum = 0.0f;
        #pragma unroll
        for (int i = 0; i < DD / 128; ++i) {   // 4 independent LDG.128
            float4 w = wrow[i * 32 + lane];
            float4 e = s_embed[i * 32 + lane];
            sum = fmaf(w.x, e.x, sum);
            sum = fmaf(w.y, e.y, sum);
            sum = fmaf(w.z, e.z, sum);
            sum = fmaf(w.w, e.w, sum);
        }

        #pragma unroll
        for (int off = 16; off; off >>= 1)
            sum += __shfl_xor_sync(0xffffffffu, sum, off);

        if (lane == 0)
            out[b * KK + k] = sum + __ldg(&sp_bias[idx]);
    }
}

extern "C" void kernel_launch(void* const* d_in, const int* in_sizes, int n_in,
                              void* d_out, int out_size) {
    const float* embed     = (const float*)d_in[0];
    const int*   shortlist = (const int*)  d_in[1];
    const float* sp_weight = (const float*)d_in[2];
    const float* sp_bias   = (const float*)d_in[3];
    float*       out       = (float*)d_out;

    fused_kernel<<<dim3(BB, NB), 256>>>(embed, shortlist, sp_weight, sp_bias, out);
}

// round 13
// speedup vs baseline: 1.3073x; 1.0339x over previous
#include <cuda_runtime.h>

#define BB 512
#define KK 800
#define DD 512
#define LL 500000
#define NB 24
#define BSZ ((LL + NB - 1) / NB)   // 20834; last bucket slightly smaller

// ---------------------------------------------------------------------------
// Single fused kernel. grid = (x=b fast, y=bucket slow), 256 threads.
// Per block (b,bucket): stage embed[b] in shared + filter this bucket's items
// out of shortlist row b (one int4 per thread, warp-aggregated compaction),
// ONE barrier, then warp-per-item float4 dot products.
//
// Linear bid order => the ~1184 concurrently-resident blocks span ~2.3
// buckets => concurrent weight footprint ~96 MB < 126 MB L2, so duplicate
// weight rows across b are L2 hits; DRAM traffic == unique rows (~573 MB),
// the floor for this problem at fp32. Plain LDG.128 (default caching) is
// deliberate: L1 serves cross-block same-SM row reuse (R10's __ldcg test
// showed bypassing L1 costs 1.15 TB/s). Minimal barriers are deliberate:
// barrier-coupling warps/blocks (R9 persistent, R11 sort) costs 10+ us.
// Bias load hoisted ahead of the weight loop so its scattered-gather latency
// hides under the weight stream instead of extending each item's tail.
// ---------------------------------------------------------------------------
__global__ __launch_bounds__(256, 8) void fused_kernel(
    const float* __restrict__ embed,
    const int*   __restrict__ shortlist,
    const float* __restrict__ sp_weight,
    const float* __restrict__ sp_bias,
    float*       __restrict__ out)
{
    __shared__ float4       s_embed[DD / 4];   // 2 KB
    __shared__ unsigned int s_list[KK];
    __shared__ int          s_cnt;

    const int b      = blockIdx.x;
    const int bucket = blockIdx.y;
    const int t      = threadIdx.x;
    const int lane   = t & 31;

    if (t == 0) s_cnt = 0;
    __syncthreads();

    // ---- overlapped prologue: embed staging + shortlist filter ----
    const float4* erow = reinterpret_cast<const float4*>(embed + (size_t)b * DD);
    if (t < DD / 4)                    // 128 threads, 1 float4 each
        s_embed[t] = erow[t];

    const int lo = bucket * BSZ;
    const int hi = lo + BSZ;           // last bucket: hi > LL harmless (idx < LL)

    const int4* srow = reinterpret_cast<const int4*>(shortlist + (size_t)b * KK);
    int4 v = make_int4(-1, -1, -1, -1);
    if (t < KK / 4)                    // 200 threads, 1 int4 each
        v = srow[t];

    // warp-aggregated compaction, component by component
    #pragma unroll
    for (int c = 0; c < 4; ++c) {
        int idx = (c == 0) ? v.x : (c == 1) ? v.y : (c == 2) ? v.z : v.w;
        bool m = (t < KK / 4) && (idx >= lo) && (idx < hi);
        unsigned bal = __ballot_sync(0xffffffffu, m);
        if (bal) {
            int base = 0;
            if (lane == 0) base = atomicAdd(&s_cnt, __popc(bal));
            base = __shfl_sync(0xffffffffu, base, 0);
            if (m) {
                int off = __popc(bal & ((1u << lane) - 1u));
                int k = t * 4 + c;
                s_list[base + off] = ((unsigned)idx << 10) | (unsigned)k;
            }
        }
    }
    __syncthreads();

    // ---- main: warp per item, float4-coalesced weight-row dot ----
    const int cnt  = s_cnt;
    const int warp = t >> 5;

    for (int j = warp; j < cnt; j += 8) {
        const unsigned int it  = s_list[j];
        const int          k   = (int)(it & 1023u);
        const long long    idx = (long long)(it >> 10);

        // issue the scattered bias gather early; consumed after the reduction
        float bias = 0.0f;
        if (lane == 0) bias = __ldg(&sp_bias[idx]);

        const float4* wrow =
            reinterpret_cast<const float4*>(sp_weight + idx * DD);

        float sum = 0.0f;
        #pragma unroll
        for (int i = 0; i < DD / 128; ++i) {   // 4 independent LDG.128
            float4 w = wrow[i * 32 + lane];
            float4 e = s_embed[i * 32 + lane];
            sum = fmaf(w.x, e.x, sum);
            sum = fmaf(w.y, e.y, sum);
            sum = fmaf(w.z, e.z, sum);
            sum = fmaf(w.w, e.w, sum);
        }

        #pragma unroll
        for (int off = 16; off; off >>= 1)
            sum += __shfl_xor_sync(0xffffffffu, sum, off);

        if (lane == 0)
            out[b * KK + k] = sum + bias;
    }
}

extern "C" void kernel_launch(void* const* d_in, const int* in_sizes, int n_in,
                              void* d_out, int out_size) {
    const float* embed     = (const float*)d_in[0];
    const int*   shortlist = (const int*)  d_in[1];
    const float* sp_weight = (const float*)d_in[2];
    const float* sp_bias   = (const float*)d_in[3];
    float*       out       = (float*)d_out;

    fused_kernel<<<dim3(BB, NB), 256>>>(embed, shortlist, sp_weight, sp_bias, out);
}